// round 12
// baseline (speedup 1.0000x reference)
#include <cuda_runtime.h>
#include <cuda_fp16.h>
#include <cstdint>

#define N_TOK 4096
#define HDIM  1024
#define NEXP  16
#define TM 128
#define TN 256
#define TK 32                  // halves per k-tile
#define NT 4
#define KTILES (HDIM / TK)     // 32
#define SLDH 40                // 80B row stride: conflict-free for ldmatrix
#define A_HALVES (TM * SLDH)
#define A_BYTES  (A_HALVES * 2)
#define STAGE_HALVES ((TM + TN) * SLDH)
#define STAGE_BYTES  (STAGE_HALVES * 2)    // 30720
#define NSTAGE 6
#define SMEM_TOTAL (NSTAGE * STAGE_BYTES)  // 184320

#define NGATE 256
#define NCONV 928

__device__ int    g_top2_idx[N_TOK * 2];
__device__ float  g_top2_w[N_TOK * 2];
__device__ int    g_slot[N_TOK * 2];
__device__ int    g_counts[NEXP];
__device__ int    g_offsets[NEXP];
__device__ int    g_mtp[NEXP + 1];
__device__ int    g_units_total;
__device__ int    g_unit_ctr;
__device__ int    g_tok[2 * N_TOK];
__device__ __half g_staging[(size_t)2 * N_TOK * HDIM];
__device__ __half g_wh[(size_t)NEXP * HDIM * HDIM];
__device__ __half g_tokh[(size_t)N_TOK * HDIM];

// ---------- prep: gate (+ fp16 token write) fused with expert_w convert ----------
__global__ void __launch_bounds__(512)
prep_kernel(const float* __restrict__ tokens, const float* __restrict__ gate_w,
            const float* __restrict__ expert_w) {
    if (blockIdx.x >= NGATE) {
        const size_t stride = (size_t)NCONV * 512;
        size_t i = (size_t)(blockIdx.x - NGATE) * 512 + threadIdx.x;
        const size_t nw = (size_t)NEXP * HDIM * HDIM / 4;
        const float4* w4 = (const float4*)expert_w;
        for (size_t j = i; j < nw; j += stride) {
            float4 v = w4[j];
            __half2 h0 = __floats2half2_rn(v.x, v.y);
            __half2 h1 = __floats2half2_rn(v.z, v.w);
            *(uint2*)(g_wh + j * 4) = make_uint2(*(uint32_t*)&h0, *(uint32_t*)&h1);
        }
        return;
    }
    const int w = threadIdx.x >> 5;
    const int lane = threadIdx.x & 31;
    const int tok0 = blockIdx.x * 16;

    float4 wreg[8];
    const float4* gw = (const float4*)(gate_w + (size_t)w * HDIM);
#pragma unroll
    for (int i = 0; i < 8; i++) wreg[i] = gw[lane + i * 32];

    __shared__ float lg[16][NEXP + 1];
    for (int t = 0; t < 16; t++) {
        const float4* x = (const float4*)(tokens + (size_t)(tok0 + t) * HDIM);
        float s = 0.f;
#pragma unroll
        for (int i = 0; i < 8; i++) {
            float4 a = x[lane + i * 32];
            s += a.x * wreg[i].x + a.y * wreg[i].y + a.z * wreg[i].z + a.w * wreg[i].w;
        }
#pragma unroll
        for (int o = 16; o; o >>= 1) s += __shfl_xor_sync(0xffffffffu, s, o);
        if (lane == 0) lg[t][w] = s;
    }
    {
        const float4* t4 = (const float4*)(tokens + (size_t)tok0 * HDIM);
        __half* th = g_tokh + (size_t)tok0 * HDIM;
#pragma unroll
        for (int j = 0; j < 8; j++) {
            int idx = threadIdx.x + j * 512;
            float4 v = t4[idx];
            __half2 h0 = __floats2half2_rn(v.x, v.y);
            __half2 h1 = __floats2half2_rn(v.z, v.w);
            *(uint2*)(th + idx * 4) = make_uint2(*(uint32_t*)&h0, *(uint32_t*)&h1);
        }
    }
    __syncthreads();

    if (threadIdx.x < 16) {
        const int t = threadIdx.x;
        const int n = tok0 + t;
        float mx = lg[t][0];
#pragma unroll
        for (int e = 1; e < NEXP; e++) mx = fmaxf(mx, lg[t][e]);
        float p[NEXP], sum = 0.f;
#pragma unroll
        for (int e = 0; e < NEXP; e++) { p[e] = expf(lg[t][e] - mx); sum += p[e]; }
        float b1 = -1.f, b2 = -1.f; int i1 = 0, i2 = 0;
#pragma unroll
        for (int e = 0; e < NEXP; e++) {
            float v = p[e];
            if (v > b1)      { b2 = b1; i2 = i1; b1 = v; i1 = e; }
            else if (v > b2) { b2 = v;  i2 = e; }
        }
        float inv = 1.f / sum;
        g_top2_idx[n * 2 + 0] = i1;
        g_top2_idx[n * 2 + 1] = i2;
        g_top2_w[n * 2 + 0] = b1 * inv;
        g_top2_w[n * 2 + 1] = b2 * inv;
    }
}

// ---------- route: count + scan + scatter ----------
__global__ void __launch_bounds__(512)
route_kernel() {
    __shared__ int hist[16][NEXP];
    __shared__ int s_fill[NEXP];
    const int tid = threadIdx.x, wid = tid >> 5, lane = tid & 31;
    if (tid < 16 * NEXP) ((int*)hist)[tid] = 0;
    if (tid < NEXP) s_fill[tid] = 0;
    __syncthreads();
    for (int i = tid; i < 2 * N_TOK; i += 512)
        atomicAdd(&hist[wid][g_top2_idx[i]], 1);
    __syncthreads();
    if (tid < NEXP) {
        int c = 0;
#pragma unroll
        for (int r = 0; r < 16; r++) c += hist[r][tid];
        g_counts[tid] = c;
    }
    __syncthreads();
    if (tid == 0) {
        int acc = 0, accm = 0;
#pragma unroll
        for (int e = 0; e < NEXP; e++) {
            g_offsets[e] = acc; acc += g_counts[e];
            g_mtp[e] = accm;    accm += (g_counts[e] + TM - 1) / TM;
        }
        g_mtp[NEXP] = accm;
        g_units_total = accm * NT;
        g_unit_ctr = 0;
    }
    __syncthreads();
    for (int i = tid; i < 2 * N_TOK; i += 512) {
        const int e = g_top2_idx[i];
        unsigned mask = __match_any_sync(0xffffffffu, e);
        int leader = __ffs(mask) - 1;
        int lrank = __popc(mask & ((1u << lane) - 1));
        int base = 0;
        if (lane == leader) base = atomicAdd(&s_fill[e], __popc(mask));
        base = __shfl_sync(0xffffffffu, base, leader);
        int o = g_offsets[e] + base + lrank;
        g_tok[o] = i >> 1;
        g_slot[i] = o;
    }
}

// ---------- persistent fp16 grouped GEMM: 256 thr, 64x64 warp tiles ----------
__device__ __forceinline__ void cpa16(uint32_t dst, const __half* src) {
    asm volatile("cp.async.cg.shared.global [%0], [%1], 16;\n" :: "r"(dst), "l"(src));
}
__device__ __forceinline__ void ldsm4(uint32_t& r0, uint32_t& r1, uint32_t& r2,
                                      uint32_t& r3, uint32_t a) {
    asm volatile("ldmatrix.sync.aligned.m8n8.x4.shared.b16 {%0,%1,%2,%3}, [%4];"
                 : "=r"(r0), "=r"(r1), "=r"(r2), "=r"(r3) : "r"(a));
}

__global__ void __launch_bounds__(256, 1)
moe_gemm_kernel(const float* __restrict__ expert_b) {
    extern __shared__ __half smemh[];
    __shared__ int uinfo[6];
    const uint32_t sbase = (uint32_t)__cvta_generic_to_shared(smemh);

    const int tid  = threadIdx.x;
    const int lane = tid & 31;
    const int warp = tid >> 5;
    const int g    = lane >> 2;
    const int c    = lane & 3;
    const int wm0  = (warp & 1) * 64;     // 2 warp rows x 64
    const int wn0  = (warp >> 1) * 64;    // 4 warp cols x 64

    const int grp = lane >> 3, rin = lane & 7;
    uint32_t aoff[4], boff[4];
#pragma unroll
    for (int mi = 0; mi < 4; mi++)
        aoff[mi] = (uint32_t)(((wm0 + mi * 16 + (grp & 1) * 8 + rin) * SLDH
                               + (grp >> 1) * 8) * 2);
#pragma unroll
    for (int p = 0; p < 4; p++)
        boff[p] = (uint32_t)(A_BYTES + ((wn0 + p * 16 + (grp >> 1) * 8 + rin) * SLDH
                                        + (grp & 1) * 8) * 2);

    for (;;) {
        if (tid == 0) {
            int u = atomicAdd(&g_unit_ctr, 1);
            uinfo[0] = u;
            if (u < g_units_total) {
                int nt = u & (NT - 1);
                int mu = u >> 2;
                int e = 0;
                while (mu >= g_mtp[e + 1]) e++;
                uinfo[1] = e;
                uinfo[2] = (mu - g_mtp[e]) * TM;
                uinfo[3] = nt * TN;
                uinfo[4] = g_offsets[e];
                uinfo[5] = g_counts[e];
            }
        }
        __syncthreads();
        if (uinfo[0] >= g_units_total) break;
        const int e = uinfo[1], m0 = uinfo[2], n0 = uinfo[3];
        const int base = uinfo[4], cnt = uinfo[5];

        // copy sources: 2 A chunks + 4 B chunks per thread (16B each)
        const __half* aP[2];
        const __half* bP[4];
        uint32_t offA[2], offB[4];
#pragma unroll
        for (int j = 0; j < 2; j++) {
            int id = tid + j * 256;            // 0..511 -> A rows 0..127
            int r = id >> 2, c4 = id & 3;
            offA[j] = (uint32_t)(r * 80 + c4 * 16);
            int m = m0 + r; if (m > cnt - 1) m = cnt - 1;
            aP[j] = g_tokh + ((size_t)g_tok[base + m] << 10) + c4 * 8;
        }
#pragma unroll
        for (int j = 0; j < 4; j++) {
            int id = tid + j * 256;            // 0..1023 -> B rows 0..255
            int rb = id >> 2, cb = id & 3;
            offB[j] = (uint32_t)(A_BYTES + rb * 80 + cb * 16);
            bP[j] = g_wh + ((size_t)e << 20) + ((size_t)(n0 + rb) << 10) + cb * 8;
        }

        auto issue_copy = [&](int kt) {
            uint32_t sb = sbase + (uint32_t)(kt % NSTAGE) * STAGE_BYTES;
            int ko = kt * TK;
            cpa16(sb + offA[0], aP[0] + ko);
            cpa16(sb + offA[1], aP[1] + ko);
            cpa16(sb + offB[0], bP[0] + ko);
            cpa16(sb + offB[1], bP[1] + ko);
            cpa16(sb + offB[2], bP[2] + ko);
            cpa16(sb + offB[3], bP[3] + ko);
            asm volatile("cp.async.commit_group;\n" ::: "memory");
        };

        float acc[4][8][4];
#pragma unroll
        for (int mi = 0; mi < 4; mi++)
#pragma unroll
            for (int ni = 0; ni < 8; ni++)
#pragma unroll
                for (int r = 0; r < 4; r++) acc[mi][ni][r] = 0.f;

        auto compute = [&](int kt) {
            const uint32_t stg = sbase + (uint32_t)(kt % NSTAGE) * STAGE_BYTES;
#pragma unroll
            for (int ks = 0; ks < 2; ks++) {
                const uint32_t kb = (uint32_t)(ks * 32);
                uint32_t a[4][4];
#pragma unroll
                for (int mi = 0; mi < 4; mi++)
                    ldsm4(a[mi][0], a[mi][1], a[mi][2], a[mi][3], stg + aoff[mi] + kb);
#pragma unroll
                for (int p = 0; p < 4; p++) {
                    uint32_t b0, b1, b2, b3;
                    ldsm4(b0, b1, b2, b3, stg + boff[p] + kb);
#pragma unroll
                    for (int mi = 0; mi < 4; mi++) {
                        float* d0 = acc[mi][p * 2];
                        float* d1 = acc[mi][p * 2 + 1];
                        asm volatile(
                            "mma.sync.aligned.m16n8k16.row.col.f32.f16.f16.f32 "
                            "{%0,%1,%2,%3},{%4,%5,%6,%7},{%8,%9},{%0,%1,%2,%3};\n"
                            : "+f"(d0[0]), "+f"(d0[1]), "+f"(d0[2]), "+f"(d0[3])
                            : "r"(a[mi][0]), "r"(a[mi][1]), "r"(a[mi][2]), "r"(a[mi][3]),
                              "r"(b0), "r"(b1));
                        asm volatile(
                            "mma.sync.aligned.m16n8k16.row.col.f32.f16.f16.f32 "
                            "{%0,%1,%2,%3},{%4,%5,%6,%7},{%8,%9},{%0,%1,%2,%3};\n"
                            : "+f"(d1[0]), "+f"(d1[1]), "+f"(d1[2]), "+f"(d1[3])
                            : "r"(a[mi][0]), "r"(a[mi][1]), "r"(a[mi][2]), "r"(a[mi][3]),
                              "r"(b2), "r"(b3));
                    }
                }
            }
        };

        issue_copy(0); issue_copy(1); issue_copy(2); issue_copy(3);

        for (int kt = 0; kt < KTILES; kt += 2) {
            if (kt <= KTILES - 4)
                asm volatile("cp.async.wait_group 2;\n" ::: "memory");
            else
                asm volatile("cp.async.wait_group 0;\n" ::: "memory");
            __syncthreads();
            if (kt + 5 < KTILES) { issue_copy(kt + 4); issue_copy(kt + 5); }
            compute(kt);
            compute(kt + 1);
        }

        // epilogue: relu(acc + bias) -> fp16 staging
        float2 bias2[8];
#pragma unroll
        for (int ni = 0; ni < 8; ni++) {
            int n = n0 + wn0 + ni * 8 + 2 * c;
            bias2[ni] = *(const float2*)(expert_b + (size_t)e * HDIM + n);
        }
#pragma unroll
        for (int mi = 0; mi < 4; mi++) {
#pragma unroll
            for (int half = 0; half < 2; half++) {
                int m = m0 + wm0 + mi * 16 + g + half * 8;
                if (m < cnt) {
                    __half* orow = g_staging + (size_t)(base + m) * HDIM + n0 + wn0 + 2 * c;
#pragma unroll
                    for (int ni = 0; ni < 8; ni++) {
                        float v0 = fmaxf(acc[mi][ni][half * 2 + 0] + bias2[ni].x, 0.f);
                        float v1 = fmaxf(acc[mi][ni][half * 2 + 1] + bias2[ni].y, 0.f);
                        __half2 h = __floats2half2_rn(v0, v1);
                        *(uint32_t*)(orow + ni * 8) = *(uint32_t*)&h;
                    }
                }
            }
        }
    }
}

// ---------- combine: grid-stride, 8 tokens per block ----------
__global__ void __launch_bounds__(256)
combine_kernel(float* __restrict__ out) {
    for (int n = blockIdx.x; n < N_TOK; n += gridDim.x) {
        const int s0 = g_slot[n * 2], s1 = g_slot[n * 2 + 1];
        const float w0 = g_top2_w[n * 2], w1 = g_top2_w[n * 2 + 1];
        const __half2* a = (const __half2*)(g_staging + (size_t)s0 * HDIM);
        const __half2* b = (const __half2*)(g_staging + (size_t)s1 * HDIM);
        float2* o = (float2*)(out + (size_t)n * HDIM);
#pragma unroll
        for (int j = 0; j < 2; j++) {
            int i = threadIdx.x + j * 256;
            float2 x = __half22float2(a[i]);
            float2 y = __half22float2(b[i]);
            o[i] = make_float2(w0 * x.x + w1 * y.x, w0 * x.y + w1 * y.y);
        }
    }
}

extern "C" void kernel_launch(void* const* d_in, const int* in_sizes, int n_in,
                              void* d_out, int out_size) {
    const float* tokens   = (const float*)d_in[0];
    const float* gate_w   = (const float*)d_in[1];
    const float* expert_w = (const float*)d_in[2];
    const float* expert_b = (const float*)d_in[3];
    float* out = (float*)d_out;

    cudaFuncSetAttribute(moe_gemm_kernel,
                         cudaFuncAttributeMaxDynamicSharedMemorySize, SMEM_TOTAL);

    prep_kernel<<<NGATE + NCONV, 512>>>(tokens, gate_w, expert_w);
    route_kernel<<<1, 512>>>();
    moe_gemm_kernel<<<148, 256, SMEM_TOTAL>>>(expert_b);
    combine_kernel<<<512, 256>>>(out);
}

// round 13
// speedup vs baseline: 1.0675x; 1.0675x over previous
#include <cuda_runtime.h>
#include <cuda_fp16.h>
#include <cstdint>

#define N_TOK 4096
#define HDIM  1024
#define NEXP  16
#define TM 128
#define TN 256
#define TK 32                   // halves per k-tile
#define NT 4
#define KTILES (HDIM / TK)      // 32
#define SLDH 40                 // 80B row stride (conflict-free ldmatrix)
#define A_STAGE_B 10240         // 128 rows * 80B
#define NSTAGE_A 4
#define B_BUF_B 20480           // 256 rows * 80B
#define OFF_B  (NSTAGE_A * A_STAGE_B)        // 40960
#define SMEM_TOTAL (OFF_B + 2 * B_BUF_B)     // 81920
#define NGATE 256

__device__ int    g_top2_idx[N_TOK * 2];
__device__ float  g_top2_w[N_TOK * 2];
__device__ int    g_slot[N_TOK * 2];
__device__ int    g_counts[NEXP];
__device__ int    g_offsets[NEXP];
__device__ int    g_mtp[NEXP + 1];
__device__ int    g_units_total;
__device__ int    g_unit_ctr;
__device__ int    g_tok[2 * N_TOK];
__device__ __half g_staging[(size_t)2 * N_TOK * HDIM];
__device__ __half g_tokh[(size_t)N_TOK * HDIM];

// ---------- prep: gate + fp16 token write (gate-only now) ----------
__global__ void __launch_bounds__(512)
prep_kernel(const float* __restrict__ tokens, const float* __restrict__ gate_w) {
    const int w = threadIdx.x >> 5;
    const int lane = threadIdx.x & 31;
    const int tok0 = blockIdx.x * 16;

    float4 wreg[8];
    const float4* gw = (const float4*)(gate_w + (size_t)w * HDIM);
#pragma unroll
    for (int i = 0; i < 8; i++) wreg[i] = gw[lane + i * 32];

    __shared__ float lg[16][NEXP + 1];
    for (int t = 0; t < 16; t++) {
        const float4* x = (const float4*)(tokens + (size_t)(tok0 + t) * HDIM);
        float s = 0.f;
#pragma unroll
        for (int i = 0; i < 8; i++) {
            float4 a = x[lane + i * 32];
            s += a.x * wreg[i].x + a.y * wreg[i].y + a.z * wreg[i].z + a.w * wreg[i].w;
        }
#pragma unroll
        for (int o = 16; o; o >>= 1) s += __shfl_xor_sync(0xffffffffu, s, o);
        if (lane == 0) lg[t][w] = s;
    }
    {
        const float4* t4 = (const float4*)(tokens + (size_t)tok0 * HDIM);
        __half* th = g_tokh + (size_t)tok0 * HDIM;
#pragma unroll
        for (int j = 0; j < 8; j++) {
            int idx = threadIdx.x + j * 512;
            float4 v = t4[idx];
            __half2 h0 = __floats2half2_rn(v.x, v.y);
            __half2 h1 = __floats2half2_rn(v.z, v.w);
            *(uint2*)(th + idx * 4) = make_uint2(*(uint32_t*)&h0, *(uint32_t*)&h1);
        }
    }
    __syncthreads();

    if (threadIdx.x < 16) {
        const int t = threadIdx.x;
        const int n = tok0 + t;
        float mx = lg[t][0];
#pragma unroll
        for (int e = 1; e < NEXP; e++) mx = fmaxf(mx, lg[t][e]);
        float p[NEXP], sum = 0.f;
#pragma unroll
        for (int e = 0; e < NEXP; e++) { p[e] = expf(lg[t][e] - mx); sum += p[e]; }
        float b1 = -1.f, b2 = -1.f; int i1 = 0, i2 = 0;
#pragma unroll
        for (int e = 0; e < NEXP; e++) {
            float v = p[e];
            if (v > b1)      { b2 = b1; i2 = i1; b1 = v; i1 = e; }
            else if (v > b2) { b2 = v;  i2 = e; }
        }
        float inv = 1.f / sum;
        g_top2_idx[n * 2 + 0] = i1;
        g_top2_idx[n * 2 + 1] = i2;
        g_top2_w[n * 2 + 0] = b1 * inv;
        g_top2_w[n * 2 + 1] = b2 * inv;
    }
}

// ---------- route: count + scan + scatter ----------
__global__ void __launch_bounds__(512)
route_kernel() {
    __shared__ int hist[16][NEXP];
    __shared__ int s_fill[NEXP];
    const int tid = threadIdx.x, wid = tid >> 5, lane = tid & 31;
    if (tid < 16 * NEXP) ((int*)hist)[tid] = 0;
    if (tid < NEXP) s_fill[tid] = 0;
    __syncthreads();
    for (int i = tid; i < 2 * N_TOK; i += 512)
        atomicAdd(&hist[wid][g_top2_idx[i]], 1);
    __syncthreads();
    if (tid < NEXP) {
        int c = 0;
#pragma unroll
        for (int r = 0; r < 16; r++) c += hist[r][tid];
        g_counts[tid] = c;
    }
    __syncthreads();
    if (tid == 0) {
        int acc = 0, accm = 0;
#pragma unroll
        for (int e = 0; e < NEXP; e++) {
            g_offsets[e] = acc; acc += g_counts[e];
            g_mtp[e] = accm;    accm += (g_counts[e] + TM - 1) / TM;
        }
        g_mtp[NEXP] = accm;
        g_units_total = accm * NT;
        g_unit_ctr = 0;
    }
    __syncthreads();
    for (int i = tid; i < 2 * N_TOK; i += 512) {
        const int e = g_top2_idx[i];
        unsigned mask = __match_any_sync(0xffffffffu, e);
        int leader = __ffs(mask) - 1;
        int lrank = __popc(mask & ((1u << lane) - 1));
        int base = 0;
        if (lane == leader) base = atomicAdd(&s_fill[e], __popc(mask));
        base = __shfl_sync(0xffffffffu, base, leader);
        int o = g_offsets[e] + base + lrank;
        g_tok[o] = i >> 1;
        g_slot[i] = o;
    }
}

// ---------- persistent fp16 GEMM: B converted fp32->fp16 in-kernel ----------
__device__ __forceinline__ void cpa16(uint32_t dst, const __half* src) {
    asm volatile("cp.async.cg.shared.global [%0], [%1], 16;\n" :: "r"(dst), "l"(src));
}
__device__ __forceinline__ void ldsm4(uint32_t& r0, uint32_t& r1, uint32_t& r2,
                                      uint32_t& r3, uint32_t a) {
    asm volatile("ldmatrix.sync.aligned.m8n8.x4.shared.b16 {%0,%1,%2,%3}, [%4];"
                 : "=r"(r0), "=r"(r1), "=r"(r2), "=r"(r3) : "r"(a));
}

__global__ void __launch_bounds__(256, 1)
moe_gemm_kernel(const float* __restrict__ expert_w,
                const float* __restrict__ expert_b) {
    extern __shared__ __half smemh[];
    __shared__ int uinfo[6];
    const uint32_t sbase = (uint32_t)__cvta_generic_to_shared(smemh);

    const int tid  = threadIdx.x;
    const int lane = tid & 31;
    const int warp = tid >> 5;
    const int g    = lane >> 2;
    const int c    = lane & 3;
    const int wm0  = (warp & 1) * 64;
    const int wn0  = (warp >> 1) * 64;

    const int grp = lane >> 3, rin = lane & 7;
    uint32_t aoff[4], boff[4];
#pragma unroll
    for (int mi = 0; mi < 4; mi++)
        aoff[mi] = (uint32_t)((wm0 + mi * 16 + (grp & 1) * 8 + rin) * 80
                              + (grp >> 1) * 16);
#pragma unroll
    for (int p = 0; p < 4; p++)
        boff[p] = (uint32_t)(OFF_B + (wn0 + p * 16 + (grp >> 1) * 8 + rin) * 80
                             + (grp & 1) * 16);

    // B copy geometry (constant): thread j-th chunk handles row, segpair
    int brow[4], bsp[4];
    uint32_t offBs[4];
#pragma unroll
    for (int j = 0; j < 4; j++) {
        int id = tid + j * 256;
        brow[j] = id >> 2;           // 0..255
        bsp[j]  = id & 3;            // 16B fp16 segpair
        offBs[j] = (uint32_t)(OFF_B + brow[j] * 80 + bsp[j] * 16);
    }

    for (;;) {
        if (tid == 0) {
            int u = atomicAdd(&g_unit_ctr, 1);
            uinfo[0] = u;
            if (u < g_units_total) {
                int nt = u & (NT - 1);
                int mu = u >> 2;
                int e = 0;
                while (mu >= g_mtp[e + 1]) e++;
                uinfo[1] = e;
                uinfo[2] = (mu - g_mtp[e]) * TM;
                uinfo[3] = nt * TN;
                uinfo[4] = g_offsets[e];
                uinfo[5] = g_counts[e];
            }
        }
        __syncthreads();
        if (uinfo[0] >= g_units_total) break;
        const int e = uinfo[1], m0 = uinfo[2], n0 = uinfo[3];
        const int base = uinfo[4], cnt = uinfo[5];

        // A sources (fp16 tokens, cp.async)
        const __half* aP[2];
        uint32_t offA[2];
#pragma unroll
        for (int j = 0; j < 2; j++) {
            int id = tid + j * 256;
            int r = id >> 2, c4 = id & 3;
            offA[j] = (uint32_t)(r * 80 + c4 * 16);
            int m = m0 + r; if (m > cnt - 1) m = cnt - 1;
            aP[j] = g_tokh + ((size_t)g_tok[base + m] << 10) + c4 * 8;
        }
        // B sources (fp32 weights)
        const float4* bQ[4];
#pragma unroll
        for (int j = 0; j < 4; j++)
            bQ[j] = (const float4*)expert_w + ((size_t)e << 18)
                    + (size_t)(n0 + brow[j]) * 256 + bsp[j] * 2;

        auto issue_A = [&](int kt) {
            uint32_t sb = sbase + (uint32_t)(kt & (NSTAGE_A - 1)) * A_STAGE_B;
            int ko = kt * TK;
            cpa16(sb + offA[0], aP[0] + ko);
            cpa16(sb + offA[1], aP[1] + ko);
            asm volatile("cp.async.commit_group;\n" ::: "memory");
        };

        float4 br0[4], br1[4];
        auto loadB = [&](int kt) {
#pragma unroll
            for (int j = 0; j < 4; j++) {
                br0[j] = bQ[j][kt * 8];
                br1[j] = bQ[j][kt * 8 + 1];
            }
        };
        auto stsB = [&](int buf) {
            uint32_t bb = sbase + (uint32_t)buf * B_BUF_B;
#pragma unroll
            for (int j = 0; j < 4; j++) {
                __half2 h0 = __floats2half2_rn(br0[j].x, br0[j].y);
                __half2 h1 = __floats2half2_rn(br0[j].z, br0[j].w);
                __half2 h2 = __floats2half2_rn(br1[j].x, br1[j].y);
                __half2 h3 = __floats2half2_rn(br1[j].z, br1[j].w);
                asm volatile("st.shared.v4.b32 [%0], {%1,%2,%3,%4};"
                             :: "r"(bb + offBs[j]),
                                "r"(*(uint32_t*)&h0), "r"(*(uint32_t*)&h1),
                                "r"(*(uint32_t*)&h2), "r"(*(uint32_t*)&h3)
                             : "memory");
            }
        };

        float acc[4][8][4];
#pragma unroll
        for (int mi = 0; mi < 4; mi++)
#pragma unroll
            for (int ni = 0; ni < 8; ni++)
#pragma unroll
                for (int r = 0; r < 4; r++) acc[mi][ni][r] = 0.f;

        auto compute = [&](int kt) {
            const uint32_t stgA = sbase + (uint32_t)(kt & (NSTAGE_A - 1)) * A_STAGE_B;
            const uint32_t bufB = sbase + (uint32_t)(kt & 1) * B_BUF_B;
#pragma unroll
            for (int ks = 0; ks < 2; ks++) {
                const uint32_t kb = (uint32_t)(ks * 32);
                uint32_t a[4][4];
#pragma unroll
                for (int mi = 0; mi < 4; mi++)
                    ldsm4(a[mi][0], a[mi][1], a[mi][2], a[mi][3],
                          stgA + aoff[mi] + kb);
#pragma unroll
                for (int p = 0; p < 4; p++) {
                    uint32_t b0, b1, b2, b3;
                    ldsm4(b0, b1, b2, b3, bufB + (boff[p] - OFF_B) + OFF_B + kb);
#pragma unroll
                    for (int mi = 0; mi < 4; mi++) {
                        float* d0 = acc[mi][p * 2];
                        float* d1 = acc[mi][p * 2 + 1];
                        asm volatile(
                            "mma.sync.aligned.m16n8k16.row.col.f32.f16.f16.f32 "
                            "{%0,%1,%2,%3},{%4,%5,%6,%7},{%8,%9},{%0,%1,%2,%3};\n"
                            : "+f"(d0[0]), "+f"(d0[1]), "+f"(d0[2]), "+f"(d0[3])
                            : "r"(a[mi][0]), "r"(a[mi][1]), "r"(a[mi][2]), "r"(a[mi][3]),
                              "r"(b0), "r"(b1));
                        asm volatile(
                            "mma.sync.aligned.m16n8k16.row.col.f32.f16.f16.f32 "
                            "{%0,%1,%2,%3},{%4,%5,%6,%7},{%8,%9},{%0,%1,%2,%3};\n"
                            : "+f"(d1[0]), "+f"(d1[1]), "+f"(d1[2]), "+f"(d1[3])
                            : "r"(a[mi][0]), "r"(a[mi][1]), "r"(a[mi][2]), "r"(a[mi][3]),
                              "r"(b2), "r"(b3));
                    }
                }
            }
        };

        loadB(0);
        issue_A(0); issue_A(1); issue_A(2);

        for (int kt = 0; kt < KTILES; kt++) {
            stsB(kt & 1);
            if (kt + 1 < KTILES) loadB(kt + 1);
            if (kt <= KTILES - 3)
                asm volatile("cp.async.wait_group 2;\n" ::: "memory");
            else if (kt == KTILES - 2)
                asm volatile("cp.async.wait_group 1;\n" ::: "memory");
            else
                asm volatile("cp.async.wait_group 0;\n" ::: "memory");
            __syncthreads();
            if (kt + 3 < KTILES) issue_A(kt + 3);
            compute(kt);
            if (kt + 1 < KTILES) __syncthreads();   // B buf WAR: next stsB overwrites (kt+1)&1
        }

        // epilogue: relu(acc + bias) -> fp16 staging
        float2 bias2[8];
#pragma unroll
        for (int ni = 0; ni < 8; ni++) {
            int n = n0 + wn0 + ni * 8 + 2 * c;
            bias2[ni] = *(const float2*)(expert_b + (size_t)e * HDIM + n);
        }
#pragma unroll
        for (int mi = 0; mi < 4; mi++) {
#pragma unroll
            for (int half = 0; half < 2; half++) {
                int m = m0 + wm0 + mi * 16 + g + half * 8;
                if (m < cnt) {
                    __half* orow = g_staging + (size_t)(base + m) * HDIM + n0 + wn0 + 2 * c;
#pragma unroll
                    for (int ni = 0; ni < 8; ni++) {
                        float v0 = fmaxf(acc[mi][ni][half * 2 + 0] + bias2[ni].x, 0.f);
                        float v1 = fmaxf(acc[mi][ni][half * 2 + 1] + bias2[ni].y, 0.f);
                        __half2 h = __floats2half2_rn(v0, v1);
                        *(uint32_t*)(orow + ni * 8) = *(uint32_t*)&h;
                    }
                }
            }
        }
    }
}

// ---------- combine (one token per block — measured fastest) ----------
__global__ void __launch_bounds__(256)
combine_kernel(float* __restrict__ out) {
    const int n = blockIdx.x;
    const int s0 = g_slot[n * 2], s1 = g_slot[n * 2 + 1];
    const float w0 = g_top2_w[n * 2], w1 = g_top2_w[n * 2 + 1];
    const __half2* a = (const __half2*)(g_staging + (size_t)s0 * HDIM);
    const __half2* b = (const __half2*)(g_staging + (size_t)s1 * HDIM);
    float2* o = (float2*)(out + (size_t)n * HDIM);
#pragma unroll
    for (int j = 0; j < 2; j++) {
        int i = threadIdx.x + j * 256;
        float2 x = __half22float2(a[i]);
        float2 y = __half22float2(b[i]);
        o[i] = make_float2(w0 * x.x + w1 * y.x, w0 * x.y + w1 * y.y);
    }
}

extern "C" void kernel_launch(void* const* d_in, const int* in_sizes, int n_in,
                              void* d_out, int out_size) {
    const float* tokens   = (const float*)d_in[0];
    const float* gate_w   = (const float*)d_in[1];
    const float* expert_w = (const float*)d_in[2];
    const float* expert_b = (const float*)d_in[3];
    float* out = (float*)d_out;

    cudaFuncSetAttribute(moe_gemm_kernel,
                         cudaFuncAttributeMaxDynamicSharedMemorySize, SMEM_TOTAL);

    prep_kernel<<<NGATE, 512>>>(tokens, gate_w);
    route_kernel<<<1, 512>>>();
    moe_gemm_kernel<<<148, 256, SMEM_TOTAL>>>(expert_w, expert_b);
    combine_kernel<<<N_TOK, 256>>>(out);
}